// round 14
// baseline (speedup 1.0000x reference)
#include <cuda_runtime.h>

// RoPE (interleaved pairs), x:(B=4,H=16,S=4096,D=64) fp32, pos:(B,S) i32/i64.
//
// Flat roofline kernel (R12 shape) + occupancy push:
//   - __launch_bounds__(256, 8): force <=32 regs -> 8 CTAs/SM resident.
//   - per thread: one (b,s,j) slot x 4 heads {hq, hq+4, hq+8, hq+12};
//     4 front-batched LDG.128 (MLP_p1=4), one sincosf pair amortized 4x.
//   - single pos load (address selected by uniform, L1-hot probe word) to
//     save 2 registers vs dual-candidate scheme.
//   - plain __ldg loads, __stcs stores (best-measured policy combo).

#define S_LEN 4096
#define HSTRIDE4 (4 * 4096 * 16)   // 4-head stride in float4s = 262144

// Correctly-rounded 10^(-k/8) — matches reference's fp32 angle_rates.
__constant__ float c_rates[32] = {
    1.0f,
    0.7498942093324559f,
    0.5623413251903491f,
    0.4216965034285822f,
    0.31622776601683794f,
    0.23713737056616552f,
    0.17782794100389228f,
    0.1333521432163324f,
    0.1f,
    0.07498942093324558f,
    0.05623413251903491f,
    0.04216965034285822f,
    0.031622776601683794f,
    0.023713737056616552f,
    0.017782794100389228f,
    0.01333521432163324f,
    0.01f,
    0.007498942093324559f,
    0.005623413251903491f,
    0.004216965034285822f,
    0.0031622776601683794f,
    0.0023713737056616554f,
    0.0017782794100389228f,
    0.001333521432163324f,
    0.001f,
    0.0007498942093324558f,
    0.0005623413251903491f,
    0.0004216965034285822f,
    0.00031622776601683794f,
    0.00023713737056616553f,
    0.00017782794100389227f,
    0.0001333521432163324f
};

__global__ void __launch_bounds__(256, 8)
rope_kernel(const float4* __restrict__ x,
            const int* __restrict__ pos32,
            float4* __restrict__ out,
            int nthreads)
{
    int tid = blockIdx.x * blockDim.x + threadIdx.x;
    if (tid >= nthreads) return;

    // tid -> (b, hq in [0,4), s, j)
    int j  = tid & 15;
    int s  = (tid >> 4) & (S_LEN - 1);
    int hq = (tid >> 16) & 3;
    int b  = tid >> 18;

    // Uniform dtype probe (L1-hot broadcast), then a single pos load.
    int probe = __ldg(&pos32[16383]);     // ==0 iff buffer is int64
    int pidx  = (b << 12) | s;
    int pword = (probe == 0) ? (pidx << 1) : pidx;  // i64: value fits low word
    float p = (float)__ldg(&pos32[pword]);

    int base = (((((b << 4) | hq) << 12) | s) << 4) | j;

    // Front-batched loads: 4 independent LDG.128.
    float4 v0 = __ldg(&x[base]);
    float4 v1 = __ldg(&x[base +     HSTRIDE4]);
    float4 v2 = __ldg(&x[base + 2 * HSTRIDE4]);
    float4 v3 = __ldg(&x[base + 3 * HSTRIDE4]);

    int k0 = j << 1;
    float a0 = p * c_rates[k0];
    float a1 = p * c_rates[k0 + 1];
    float s0, c0, s1, c1;
    sincosf(a0, &s0, &c0);
    sincosf(a1, &s1, &c1);

    float4 o;
#define ROT_STORE(v, off)                          \
    o.x = c0 * (v).x - s0 * (v).y;                 \
    o.y = s0 * (v).x + c0 * (v).y;                 \
    o.z = c1 * (v).z - s1 * (v).w;                 \
    o.w = s1 * (v).z + c1 * (v).w;                 \
    __stcs(&out[off], o);

    ROT_STORE(v0, base);
    ROT_STORE(v1, base +     HSTRIDE4);
    ROT_STORE(v2, base + 2 * HSTRIDE4);
    ROT_STORE(v3, base + 3 * HSTRIDE4);
#undef ROT_STORE
}

extern "C" void kernel_launch(void* const* d_in, const int* in_sizes, int n_in,
                              void* d_out, int out_size)
{
    // Identify operands by element count (robust to harness input order).
    const float4* x     = nullptr;
    const int*    pos32 = nullptr;
    for (int i = 0; i < n_in; i++) {
        if (in_sizes[i] == 16777216)   x     = (const float4*)d_in[i];
        else if (in_sizes[i] == 16384) pos32 = (const int*)d_in[i];
    }
    float4* out = (float4*)d_out;

    int total4   = out_size / 4;          // 4,194,304 float4s
    int nthreads = total4 / 4;            // 4 float4s per thread
    int threads  = 256;
    int blocks   = (nthreads + threads - 1) / threads;
    rope_kernel<<<blocks, threads>>>(x, pos32, out, nthreads);
}

// round 15
// speedup vs baseline: 1.1722x; 1.1722x over previous
#include <cuda_runtime.h>

// RoPE (interleaved pairs), x:(B=4,H=16,S=4096,D=64) fp32, pos:(B,S) i32/i64.
//
// FINAL / champion config (measured optimum across 11 variants):
//   - per thread: one (b,s,j) slot x 4 heads {hq, hq+4, hq+8, hq+12};
//     4 front-batched LDG.128 (MLP_p1=4), one sincosf pair amortized 4x.
//     36 regs, occ ~60-62%: the measured sweet spot (MLP x occupancy max).
//   - __ldcs on x (single-use), plain write-back stores.
//   - pos dtype (i32 vs i64) probed inline; probe + both candidate words
//     loaded in parallel, select in registers (no serial chain).
//   - kernel ~18.6us = ~7.2 TB/s combined memory throughput (mixed-stream
//     HBM roofline); all other structures (MLP8, TMA pipeline, v8 loads,
//     persistent grid, forced occ8) measured slower.

#define S_LEN 4096
#define HSTRIDE4 (4 * 4096 * 16)   // 4-head stride in float4s = 262144

// Correctly-rounded 10^(-k/8) — matches reference's fp32 angle_rates.
__constant__ float c_rates[32] = {
    1.0f,
    0.7498942093324559f,
    0.5623413251903491f,
    0.4216965034285822f,
    0.31622776601683794f,
    0.23713737056616552f,
    0.17782794100389228f,
    0.1333521432163324f,
    0.1f,
    0.07498942093324558f,
    0.05623413251903491f,
    0.04216965034285822f,
    0.031622776601683794f,
    0.023713737056616552f,
    0.017782794100389228f,
    0.01333521432163324f,
    0.01f,
    0.007498942093324559f,
    0.005623413251903491f,
    0.004216965034285822f,
    0.0031622776601683794f,
    0.0023713737056616554f,
    0.0017782794100389228f,
    0.001333521432163324f,
    0.001f,
    0.0007498942093324558f,
    0.0005623413251903491f,
    0.0004216965034285822f,
    0.00031622776601683794f,
    0.00023713737056616553f,
    0.00017782794100389227f,
    0.0001333521432163324f
};

__global__ void __launch_bounds__(256)
rope_kernel(const float4* __restrict__ x,
            const int* __restrict__ pos32,
            float4* __restrict__ out,
            int nthreads)
{
    int tid = blockIdx.x * blockDim.x + threadIdx.x;
    if (tid >= nthreads) return;

    // tid -> (b, hq in [0,4), s, j)
    int j  = tid & 15;
    int s  = (tid >> 4) & (S_LEN - 1);
    int hq = (tid >> 16) & 3;
    int b  = tid >> 18;

    int pidx = (b << 12) | s;

    // Three independent loads issued together (no serial chain):
    //   probe word, i32-candidate pos, i64-candidate pos (low word).
    int probe = __ldg(&pos32[16383]);     // ==0 iff buffer is int64
    int p_i32 = __ldg(&pos32[pidx]);
    int p_i64 = __ldg(&pos32[pidx << 1]);

    int base = (((((b << 4) | hq) << 12) | s) << 4) | j;

    // Front-batched loads: 4 independent LDG.128 in flight.
    float4 v0 = __ldcs(&x[base]);
    float4 v1 = __ldcs(&x[base +     HSTRIDE4]);
    float4 v2 = __ldcs(&x[base + 2 * HSTRIDE4]);
    float4 v3 = __ldcs(&x[base + 3 * HSTRIDE4]);

    float p = (float)((probe == 0) ? p_i64 : p_i32);

    int k0 = j << 1;
    float a0 = p * c_rates[k0];
    float a1 = p * c_rates[k0 + 1];
    float s0, c0, s1, c1;
    sincosf(a0, &s0, &c0);
    sincosf(a1, &s1, &c1);

    float4 o;
#define ROT_STORE(v, off)                          \
    o.x = c0 * (v).x - s0 * (v).y;                 \
    o.y = s0 * (v).x + c0 * (v).y;                 \
    o.z = c1 * (v).z - s1 * (v).w;                 \
    o.w = s1 * (v).z + c1 * (v).w;                 \
    out[off] = o;

    ROT_STORE(v0, base);
    ROT_STORE(v1, base +     HSTRIDE4);
    ROT_STORE(v2, base + 2 * HSTRIDE4);
    ROT_STORE(v3, base + 3 * HSTRIDE4);
#undef ROT_STORE
}

extern "C" void kernel_launch(void* const* d_in, const int* in_sizes, int n_in,
                              void* d_out, int out_size)
{
    // Identify operands by element count (robust to harness input order).
    const float4* x     = nullptr;
    const int*    pos32 = nullptr;
    for (int i = 0; i < n_in; i++) {
        if (in_sizes[i] == 16777216)   x     = (const float4*)d_in[i];
        else if (in_sizes[i] == 16384) pos32 = (const int*)d_in[i];
    }
    float4* out = (float4*)d_out;

    int total4   = out_size / 4;          // 4,194,304 float4s
    int nthreads = total4 / 4;            // 4 float4s per thread
    int threads  = 256;
    int blocks   = (nthreads + threads - 1) / threads;
    rope_kernel<<<blocks, threads>>>(x, pos32, out, nthreads);
}

// round 16
// speedup vs baseline: 1.1793x; 1.0061x over previous
#include <cuda_runtime.h>

// RoPE (interleaved pairs), x:(B=4,H=16,S=4096,D=64) fp32, pos:(B,S) i32/i64.
//
// FINAL / champion config (measured optimum across 12 variants, re-validated):
//   - per thread: one (b,s,j) slot x 4 heads {hq, hq+4, hq+8, hq+12};
//     4 front-batched LDG.128 (MLP_p1=4), one sincosf pair amortized 4x.
//     36 regs, occ ~60-62%: the measured sweet spot (MLP x occupancy max).
//   - __ldcs on x (single-use), plain write-back stores.
//   - pos dtype (i32 vs i64) probed inline; probe + both candidate words
//     loaded in parallel, select in registers (no serial chain).
//   - kernel ~18.6us = ~7.2 TB/s combined memory throughput: mixed-stream
//     HBM roofline. Falsified alternatives: MLP8 (occ trade), TMA smem
//     pipeline (sync serialization), v8+evict_last (slow load path),
//     L2 policy steering (neutral), persistent grid (reg bloat),
//     forced 8 CTAs/SM (per-thread MLP loss).

#define S_LEN 4096
#define HSTRIDE4 (4 * 4096 * 16)   // 4-head stride in float4s = 262144

// Correctly-rounded 10^(-k/8) — matches reference's fp32 angle_rates.
__constant__ float c_rates[32] = {
    1.0f,
    0.7498942093324559f,
    0.5623413251903491f,
    0.4216965034285822f,
    0.31622776601683794f,
    0.23713737056616552f,
    0.17782794100389228f,
    0.1333521432163324f,
    0.1f,
    0.07498942093324558f,
    0.05623413251903491f,
    0.04216965034285822f,
    0.031622776601683794f,
    0.023713737056616552f,
    0.017782794100389228f,
    0.01333521432163324f,
    0.01f,
    0.007498942093324559f,
    0.005623413251903491f,
    0.004216965034285822f,
    0.0031622776601683794f,
    0.0023713737056616554f,
    0.0017782794100389228f,
    0.001333521432163324f,
    0.001f,
    0.0007498942093324558f,
    0.0005623413251903491f,
    0.0004216965034285822f,
    0.00031622776601683794f,
    0.00023713737056616553f,
    0.00017782794100389227f,
    0.0001333521432163324f
};

__global__ void __launch_bounds__(256)
rope_kernel(const float4* __restrict__ x,
            const int* __restrict__ pos32,
            float4* __restrict__ out,
            int nthreads)
{
    int tid = blockIdx.x * blockDim.x + threadIdx.x;
    if (tid >= nthreads) return;

    // tid -> (b, hq in [0,4), s, j)
    int j  = tid & 15;
    int s  = (tid >> 4) & (S_LEN - 1);
    int hq = (tid >> 16) & 3;
    int b  = tid >> 18;

    int pidx = (b << 12) | s;

    // Three independent loads issued together (no serial chain):
    //   probe word, i32-candidate pos, i64-candidate pos (low word).
    int probe = __ldg(&pos32[16383]);     // ==0 iff buffer is int64
    int p_i32 = __ldg(&pos32[pidx]);
    int p_i64 = __ldg(&pos32[pidx << 1]);

    int base = (((((b << 4) | hq) << 12) | s) << 4) | j;

    // Front-batched loads: 4 independent LDG.128 in flight.
    float4 v0 = __ldcs(&x[base]);
    float4 v1 = __ldcs(&x[base +     HSTRIDE4]);
    float4 v2 = __ldcs(&x[base + 2 * HSTRIDE4]);
    float4 v3 = __ldcs(&x[base + 3 * HSTRIDE4]);

    float p = (float)((probe == 0) ? p_i64 : p_i32);

    int k0 = j << 1;
    float a0 = p * c_rates[k0];
    float a1 = p * c_rates[k0 + 1];
    float s0, c0, s1, c1;
    sincosf(a0, &s0, &c0);
    sincosf(a1, &s1, &c1);

    float4 o;
#define ROT_STORE(v, off)                          \
    o.x = c0 * (v).x - s0 * (v).y;                 \
    o.y = s0 * (v).x + c0 * (v).y;                 \
    o.z = c1 * (v).z - s1 * (v).w;                 \
    o.w = s1 * (v).z + c1 * (v).w;                 \
    out[off] = o;

    ROT_STORE(v0, base);
    ROT_STORE(v1, base +     HSTRIDE4);
    ROT_STORE(v2, base + 2 * HSTRIDE4);
    ROT_STORE(v3, base + 3 * HSTRIDE4);
#undef ROT_STORE
}

extern "C" void kernel_launch(void* const* d_in, const int* in_sizes, int n_in,
                              void* d_out, int out_size)
{
    // Identify operands by element count (robust to harness input order).
    const float4* x     = nullptr;
    const int*    pos32 = nullptr;
    for (int i = 0; i < n_in; i++) {
        if (in_sizes[i] == 16777216)   x     = (const float4*)d_in[i];
        else if (in_sizes[i] == 16384) pos32 = (const int*)d_in[i];
    }
    float4* out = (float4*)d_out;

    int total4   = out_size / 4;          // 4,194,304 float4s
    int nthreads = total4 / 4;            // 4 float4s per thread
    int threads  = 256;
    int blocks   = (nthreads + threads - 1) / threads;
    rope_kernel<<<blocks, threads>>>(x, pos32, out, nthreads);
}